// round 11
// baseline (speedup 1.0000x reference)
#include <cuda_runtime.h>
#include <cstdint>

// Problem constants (fixed by the reference setup_inputs)
static constexpr int B = 256;
static constexpr int R = 36;
static constexpr int T = 64;
static constexpr int D = 1024;

// ---------------- Kernel 1 tiling ----------------
static constexpr int CHUNK  = 64;          // d-elements staged per smem tile (was 128)
static constexpr int NCHUNK = D / CHUNK;   // 16
static constexpr int STRIDE = CHUNK + 4;   // 68 words: 68 % 32 == 4 -> conflict-free LDS.128

// Kernel-1 shared-memory layout (float offsets)
static constexpr int OFF_CAP  = 0;                        // 64*68 = 4352
static constexpr int OFF_IMG  = OFF_CAP + T * STRIDE;     // +36*68 = 2448
static constexpr int OFF_PART = OFF_IMG + R * STRIDE;     // 6800; 2*64*37 = 4736
static constexpr int OFF_DOTS = OFF_PART + 2 * T * 37;    // 11536; 64*37 = 2368
static constexpr int OFF_NORM = OFF_DOTS + T * 37;        // 13904; 128
static constexpr int SMEM_FLOATS = OFF_NORM + 128;        // 14032 floats = 56128 bytes
static constexpr int SMEM_BYTES  = SMEM_FLOATS * 4;       // -> 3 CTAs/SM fit (168 KB)

static constexpr int RH = R / 2;           // 18 accumulators per warp

// Inter-kernel scratch: attn pre-duplicated as (a,a) pairs. 256*64*36*8B = 4.7 MB.
__device__ float2 g_attn[B * T * R];

// ---- packed fp32x2 helpers (sm_100+ packed fp32 pipe; ptxas never auto-fuses) ----
#define FMA2(acc, a, b) \
    asm("fma.rn.f32x2 %0, %1, %2, %0;" : "+l"(acc) : "l"(a), "l"(b))

__device__ __forceinline__ void unpackf2(long long v, float& lo, float& hi) {
    unsigned int a, b2;
    asm("mov.b64 {%0, %1}, %2;" : "=r"(a), "=r"(b2) : "l"(v));
    lo = __uint_as_float(a);
    hi = __uint_as_float(b2);
}
__device__ __forceinline__ float sumf2(long long v) {
    float lo, hi;
    unpackf2(v, lo, hi);
    return lo + hi;
}

// ================= Kernel 1: dots + norms + softmax -> g_attn =================
extern "C" __global__ void __launch_bounds__(256, 3)
scan_attn_kernel(const float* __restrict__ img,
                 const float* __restrict__ cap)
{
    extern __shared__ float sm[];
    float* capS = sm + OFF_CAP;    // [t][STRIDE]
    float* imgS = sm + OFF_IMG;    // [r][STRIDE]
    float* part = sm + OFF_PART;   // [dh][t][37]
    float* dots = sm + OFF_DOTS;   // [t][37]
    float* nrm  = sm + OFF_NORM;   // [0..35]=img norms, [36..99]=cap norms

    const int b    = blockIdx.x;
    const int tid  = threadIdx.x;
    const int warp = tid >> 5;
    const int lane = tid & 31;
    const int tg   = warp & 1;             // t-half
    const int rh   = (warp >> 1) & 1;      // r-half
    const int dh   = (warp >> 2) & 1;      // d-half (split-K of 2)
    const int myT  = (tg << 5) | lane;     // lane <-> t : conflict-free cap LDS

    const float* gImg = img + (size_t)b * R * D;
    const float* gCap = cap + (size_t)b * T * D;

    long long acc2[RH];                    // 18 packed partial dots = 36 regs
#pragma unroll
    for (int rr = 0; rr < RH; rr++) acc2[rr] = 0;
    float normAcc = 0.f;

#pragma unroll 1
    for (int c = 0; c < NCHUNK; c++) {
        const int d0 = c * CHUNK;

        // stage cap tile: 64 rows x 16 float4 (coalesced LDG.128, conflict-free STS.128)
#pragma unroll 1
        for (int i4 = tid; i4 < T * 16; i4 += 256) {
            int t = i4 >> 4, d4 = i4 & 15;
            float4 v = *(const float4*)(gCap + (size_t)t * D + d0 + 4 * d4);
            *(float4*)(capS + t * STRIDE + 4 * d4) = v;
        }
        // stage img tile: 36 rows x 16 float4
#pragma unroll 1
        for (int i4 = tid; i4 < R * 16; i4 += 256) {
            int r = i4 >> 4, d4 = i4 & 15;
            float4 v = *(const float4*)(gImg + (size_t)r * D + d0 + 4 * d4);
            *(float4*)(imgS + r * STRIDE + 4 * d4) = v;
        }
        __syncthreads();

        // fused norm accumulation from the smem tiles (no extra HBM pass)
        if (tid < R + T) {
            const float* row = (tid < R) ? (imgS + tid * STRIDE)
                                         : (capS + (tid - R) * STRIDE);
#pragma unroll
            for (int k = 0; k < 16; k++) {
                float4 v = *(const float4*)(row + 4 * k);
                normAcc += v.x * v.x + v.y * v.y + v.z * v.z + v.w * v.w;
            }
        }

        // dot accumulation: warp covers d in [dh*32, dh*32+32), r in [rh*18, rh*18+18)
        const float* capRow  = capS + myT * STRIDE + dh * 32;
        const float* imgBase = imgS + (rh * RH) * STRIDE + dh * 32;
#pragma unroll 4
        for (int j = 0; j < 8; j++) {
            longlong2 c2 = *(const longlong2*)(capRow + 4 * j);   // conflict-free LDS.128
            const float* ip = imgBase + 4 * j;
#pragma unroll
            for (int rr = 0; rr < RH; rr++) {
                longlong2 i2 = *(const longlong2*)(ip + rr * STRIDE);  // broadcast LDS.128
                FMA2(acc2[rr], i2.x, c2.x);
                FMA2(acc2[rr], i2.y, c2.y);
            }
        }
        __syncthreads();
    }

    // split-K partials: r-halves disjoint columns, d-halves the 2 reduce planes
    {
        float* pp = part + dh * (T * 37) + myT * 37 + rh * RH;
#pragma unroll
        for (int rr = 0; rr < RH; rr++) pp[rr] = sumf2(acc2[rr]);
    }
    if (tid < R + T) nrm[tid] = sqrtf(normAcc);
    __syncthreads();

    // reduce d-half partials -> dots
#pragma unroll 1
    for (int idx = tid; idx < R * T; idx += 256) {
        int t = idx / R, r = idx - t * R;
        int o = t * 37 + r;
        dots[o] = part[o] + part[T * 37 + o];
    }
    __syncthreads();

    // cosine scale + softmax over r (one thread per t), write duplicated attn pairs
    if (tid < T) {
        const float cn = nrm[R + tid];
        float s[R];
        float m = -1e30f;
#pragma unroll
        for (int r = 0; r < R; r++) {
            float denom = fmaxf(nrm[r] * cn, 1e-8f);
            s[r] = dots[tid * 37 + r] / denom;
            m = fmaxf(m, s[r]);
        }
        float sum = 0.f;
#pragma unroll
        for (int r = 0; r < R; r++) { s[r] = expf(s[r] - m); sum += s[r]; }
        float inv = 1.f / sum;
        float2* ga = g_attn + ((size_t)b * T + tid) * R;
#pragma unroll
        for (int r = 0; r < R; r++) {
            float a = s[r] * inv;
            ga[r] = make_float2(a, a);
        }
    }
}

// ============ Kernel 2: out[t][d] = sum_r attn[r][t] * img[r][d] ============
// grid = 4 d-slices x 256 batches; block 256; high occupancy (4 CTAs/SM target).
extern "C" __global__ void __launch_bounds__(256, 4)
scan_out_kernel(const float* __restrict__ img,
                float* __restrict__ out)
{
    __shared__ long long attnS[T * R];     // duplicated (a,a) pairs, 18432 B

    const int b    = blockIdx.x >> 2;      // batch
    const int q    = blockIdx.x & 3;       // d-quarter: 64 float4 per CTA
    const int tid  = threadIdx.x;
    const int warp = tid >> 5;             // t-group: 8 t per warp
    const int lane = tid & 31;

    const float* gImg = img + (size_t)b * R * D;
    float*       gOut = out + (size_t)b * T * D;
    const long long* gAt = reinterpret_cast<const long long*>(g_attn + (size_t)b * T * R);

    // stage attn tile (coalesced LDG.64)
#pragma unroll 1
    for (int i = tid; i < T * R; i += 256) attnS[i] = gAt[i];
    __syncthreads();

    const long long* at = attnS + (warp * 8) * R;

#pragma unroll 1
    for (int it = 0; it < 2; it++) {
        const int d4 = q * 64 + it * 32 + lane;    // float4 index in [0, 256)
        long long accA[8], accB[8];
#pragma unroll
        for (int s_ = 0; s_ < 8; s_++) { accA[s_] = 0; accB[s_] = 0; }

#pragma unroll 4
        for (int r = 0; r < R; r++) {
            longlong2 i2 = *(const longlong2*)(gImg + (size_t)r * D + 4 * d4);  // coalesced LDG.128
#pragma unroll
            for (int s_ = 0; s_ < 8; s_++) {
                long long a = at[s_ * R + r];       // broadcast LDS.64
                FMA2(accA[s_], i2.x, a);
                FMA2(accB[s_], i2.y, a);
            }
        }
#pragma unroll
        for (int s_ = 0; s_ < 8; s_++) {
            float4 o;
            unpackf2(accA[s_], o.x, o.y);
            unpackf2(accB[s_], o.z, o.w);
            *(float4*)(gOut + (size_t)(warp * 8 + s_) * D + 4 * d4) = o;
        }
    }
}

extern "C" void kernel_launch(void* const* d_in, const int* in_sizes, int n_in,
                              void* d_out, int out_size)
{
    const float* img = (const float*)d_in[0];   // (B, R, D) fp32
    const float* cap = (const float*)d_in[1];   // (B, T, D) fp32
    // d_in[2] = cap_mask, unused by the reference forward
    float* out = (float*)d_out;                 // (B, T, D) fp32

    cudaFuncSetAttribute(scan_attn_kernel,
                         cudaFuncAttributeMaxDynamicSharedMemorySize, SMEM_BYTES);

    scan_attn_kernel<<<B, 256, SMEM_BYTES>>>(img, cap);
    scan_out_kernel<<<B * 4, 256>>>(img, out);
}

// round 15
// speedup vs baseline: 1.9158x; 1.9158x over previous
#include <cuda_runtime.h>
#include <cuda_bf16.h>
#include <cstdint>

// Problem constants (fixed by the reference setup_inputs)
static constexpr int B = 256;
static constexpr int R = 36;
static constexpr int T = 64;
static constexpr int D = 1024;

static constexpr int KCH = 64;             // d-elements per staged chunk (128B bf16 rows)
static constexpr int NCH = D / KCH;        // 16 chunks

// Shared-memory byte offsets (within 128-aligned window)
static constexpr int OFF_CAP  = 0;                    // cap tile: 64 x 128B = 8192
static constexpr int OFF_IMG  = 8192;                 // img tile: 48 x 128B = 6144
static constexpr int OFF_SC   = 14336;                // scores fp32 [64][49] = 12544
static constexpr int OFF_NP   = 26880;                // norm partials 100x16 fp32 = 6400
static constexpr int OFF_NRM  = 33280;                // norms 100 fp32 (+pad) = 512
static constexpr int OFF_ATTN = 33792;                // attn dup (a,a): 64*36*8 = 18432
static constexpr int SMEM_BYTES = 52224 + 128;

#define SWZ(x) ((x) ^ (((x) >> 3) & 0x70))

// ---------------- helpers ----------------
__device__ __forceinline__ uint32_t smem_u32(const void* p) {
    uint32_t a;
    asm("{ .reg .u64 t; cvta.to.shared.u64 t, %1; cvt.u32.u64 %0, t; }" : "=r"(a) : "l"(p));
    return a;
}
__device__ __forceinline__ uint32_t cvt_bf2(float lo, float hi) {  // packs (lo,hi) in mem order
    uint32_t r;
    asm("cvt.rn.bf16x2.f32 %0, %1, %2;" : "=r"(r) : "f"(hi), "f"(lo));
    return r;
}
__device__ __forceinline__ void ldm_x4(uint32_t& r0, uint32_t& r1, uint32_t& r2, uint32_t& r3,
                                       uint32_t a) {
    asm volatile("ldmatrix.sync.aligned.m8n8.x4.shared.b16 {%0,%1,%2,%3}, [%4];"
                 : "=r"(r0), "=r"(r1), "=r"(r2), "=r"(r3) : "r"(a));
}
__device__ __forceinline__ void ldm_x2(uint32_t& r0, uint32_t& r1, uint32_t a) {
    asm volatile("ldmatrix.sync.aligned.m8n8.x2.shared.b16 {%0,%1}, [%2];"
                 : "=r"(r0), "=r"(r1) : "r"(a));
}
__device__ __forceinline__ void mma16816(float& d0, float& d1, float& d2, float& d3,
                                         uint32_t a0, uint32_t a1, uint32_t a2, uint32_t a3,
                                         uint32_t b0, uint32_t b1) {
    asm volatile("mma.sync.aligned.m16n8k16.row.col.f32.bf16.bf16.f32 "
                 "{%0,%1,%2,%3}, {%4,%5,%6,%7}, {%8,%9}, {%0,%1,%2,%3};"
                 : "+f"(d0), "+f"(d1), "+f"(d2), "+f"(d3)
                 : "r"(a0), "r"(a1), "r"(a2), "r"(a3), "r"(b0), "r"(b1));
}

// ---- packed fp32x2 helpers for Phase C (proven in the 150.8us kernel) ----
#define FMA2(acc, a, b) \
    asm("fma.rn.f32x2 %0, %1, %2, %0;" : "+l"(acc) : "l"(a), "l"(b))
__device__ __forceinline__ void unpackf2(long long v, float& lo, float& hi) {
    unsigned int a, b2;
    asm("mov.b64 {%0, %1}, %2;" : "=r"(a), "=r"(b2) : "l"(v));
    lo = __uint_as_float(a);
    hi = __uint_as_float(b2);
}
__device__ __forceinline__ long long packf2(float lo, float hi) {
    long long v;
    asm("mov.b64 %0, {%1, %2};" : "=l"(v) : "r"(__float_as_uint(lo)), "r"(__float_as_uint(hi)));
    return v;
}

extern "C" __global__ void __launch_bounds__(256, 2)
scan_hmma_kernel(const float* __restrict__ img,
                 const float* __restrict__ cap,
                 float* __restrict__ out)
{
    extern __shared__ char smraw[];
    const uint32_t sbase = smem_u32(smraw);
    const uint32_t abase = (sbase + 127u) & ~127u;
    char* sm = smraw + (abase - sbase);

    float*     scS   = (float*)(sm + OFF_SC);     // [64][49]
    float*     np    = (float*)(sm + OFF_NP);     // [100][16]
    float*     nrm   = (float*)(sm + OFF_NRM);    // [0..35]=img, [36..99]=cap
    long long* attn2 = (long long*)(sm + OFF_ATTN);
    const uint32_t capBase = abase + OFF_CAP;
    const uint32_t imgBase = abase + OFF_IMG;

    const int b    = blockIdx.x;
    const int tid  = threadIdx.x;
    const int warp = tid >> 5;
    const int lane = tid & 31;
    const int tt   = warp >> 1;            // t-tile: 16 rows
    const int nh   = warp & 1;             // n-half: 24 r-cols

    const float* gImg = img + (size_t)b * R * D;
    const float* gCap = cap + (size_t)b * T * D;
    float*       gOut = out + (size_t)b * T * D;

    // ---------------- Phase A: scores = cap . img^T via HMMA (bf16), norms fp32 ----------------
    float C0[4] = {0, 0, 0, 0}, C1[4] = {0, 0, 0, 0}, C2[4] = {0, 0, 0, 0};  // 3 n-tiles
    float capN[4] = {0.f, 0.f, 0.f, 0.f};
    float imgN[3] = {0.f, 0.f, 0.f};

    // ldmatrix lane addressing (tile-relative, pre-swizzle)
    // A (cap, [t][k]): lanes 0-15 -> rows tt*16+0..15 at +0B (k 0-7); lanes 16-31 -> same rows +16B (k 8-15)
    const int aRow = tt * 16 + (lane & 15);
    const int aOff = (lane >> 4) << 4;
    // B (img, [n][k], col-major B -> NON-trans):
    //   x4: lanes 0-7 -> n-rows nbase+0..7 at +0 (b0), 8-15 -> same rows +16B (b1),
    //       16-23 -> rows nbase+8..15 at +0 (b2), 24-31 -> +16B (b3)
    const int bRow = nh * 24 + (lane & 7) + ((lane >> 4) << 3);
    const int bOff = ((lane >> 3) & 1) << 4;
    //   x2: lanes 0-7 -> rows nbase+16..23 at +0, 8-15 -> +16B
    const int cRow = nh * 24 + 16 + (lane & 7);

#pragma unroll 1
    for (int c = 0; c < NCH; c++) {
        const int d0 = c * KCH;

        // stage cap tile: row = i4>>4 (fixed per m across chunks -> consistent norm rows)
#pragma unroll
        for (int m = 0; m < 4; m++) {
            const int i4  = tid + 256 * m;
            const int row = i4 >> 4, col4 = i4 & 15;
            float4 v = *(const float4*)(gCap + (size_t)row * D + d0 + 4 * col4);
            capN[m] += v.x * v.x + v.y * v.y + v.z * v.z + v.w * v.w;
            unsigned long long p = ((unsigned long long)cvt_bf2(v.z, v.w) << 32) | cvt_bf2(v.x, v.y);
            *(unsigned long long*)(sm + OFF_CAP + SWZ(row * 128 + col4 * 8)) = p;
        }
        // stage img tile (rows 0-35; rows 36-47 stale, their score columns are never read)
#pragma unroll
        for (int m = 0; m < 3; m++) {
            const int i4 = tid + 256 * m;
            if (i4 < R * 16) {
                const int row = i4 >> 4, col4 = i4 & 15;
                float4 v = *(const float4*)(gImg + (size_t)row * D + d0 + 4 * col4);
                imgN[m] += v.x * v.x + v.y * v.y + v.z * v.z + v.w * v.w;
                unsigned long long p = ((unsigned long long)cvt_bf2(v.z, v.w) << 32) | cvt_bf2(v.x, v.y);
                *(unsigned long long*)(sm + OFF_IMG + SWZ(row * 128 + col4 * 8)) = p;
            }
        }
        __syncthreads();

        // 4 K=16 MMA steps over this 64-d chunk
#pragma unroll
        for (int ks = 0; ks < 4; ks++) {
            const int kb = ks * 32;
            uint32_t a0, a1, a2, a3, b0, b1, b2, b3, b4, b5;
            ldm_x4(a0, a1, a2, a3, capBase + SWZ(aRow * 128 + kb + aOff));
            ldm_x4(b0, b1, b2, b3, imgBase + SWZ(bRow * 128 + kb + bOff));
            ldm_x2(b4, b5,         imgBase + SWZ(cRow * 128 + kb + bOff));
            mma16816(C0[0], C0[1], C0[2], C0[3], a0, a1, a2, a3, b0, b1);
            mma16816(C1[0], C1[1], C1[2], C1[3], a0, a1, a2, a3, b2, b3);
            mma16816(C2[0], C2[1], C2[2], C2[3], a0, a1, a2, a3, b4, b5);
        }
        __syncthreads();   // ldmatrix done -> tiles reusable
    }

    // write C frags -> scores[t][r] (stride 49)
    {
        const int row0 = tt * 16 + (lane >> 2);
        const int col0 = nh * 24 + (lane & 3) * 2;
        float* s0 = scS + row0 * 49 + col0;
        float* s8 = s0 + 8 * 49;
        s0[0] = C0[0];  s0[1] = C0[1];  s8[0] = C0[2];  s8[1] = C0[3];
        s0[8] = C1[0];  s0[9] = C1[1];  s8[8] = C1[2];  s8[9] = C1[3];
        s0[16] = C2[0]; s0[17] = C2[1]; s8[16] = C2[2]; s8[17] = C2[3];
    }
    // norm partials
    {
        const int a = tid >> 4, l = tid & 15;
#pragma unroll
        for (int m = 0; m < 4; m++) np[(R + 16 * m + a) * 16 + l] = capN[m];
        np[(0 + a) * 16 + l]  = imgN[0];
        np[(16 + a) * 16 + l] = imgN[1];
        if (tid < 64) np[(32 + a) * 16 + l] = imgN[2];
    }
    __syncthreads();
    if (tid < R + T) {
        float s = 0.f;
#pragma unroll
        for (int j = 0; j < 16; j++) s += np[tid * 16 + j];
        nrm[tid] = sqrtf(s);
    }
    __syncthreads();

    // ---------------- Phase B: cosine scale + softmax over r (thread = t) ----------------
    if (tid < T) {
        const float cn = nrm[R + tid];
        float s[R];
        float mx = -1e30f;
#pragma unroll
        for (int r = 0; r < R; r++) {
            float denom = fmaxf(nrm[r] * cn, 1e-8f);
            s[r] = scS[tid * 49 + r] / denom;
            mx = fmaxf(mx, s[r]);
        }
        float sum = 0.f;
#pragma unroll
        for (int r = 0; r < R; r++) { s[r] = expf(s[r] - mx); sum += s[r]; }
        const float inv = 1.f / sum;
#pragma unroll
        for (int r = 0; r < R; r++) {
            float a = s[r] * inv;
            attn2[tid * R + r] = packf2(a, a);
        }
    }
    __syncthreads();

    // ---------------- Phase C (verbatim from the proven 150.8us kernel) ----------------
    // out[t][d] = sum_r attn[r][t] * img[r][d]; warp <-> 8-t group, lane <-> d-float4
    {
        const int tw = warp;
        const int dd = lane;
        const long long* at = attn2 + (tw * 8) * R;
#pragma unroll 1
        for (int it = 0; it < 8; it++) {
            const int d4 = dd + 32 * it;
            long long accA[8], accB[8];
#pragma unroll
            for (int s_ = 0; s_ < 8; s_++) { accA[s_] = 0; accB[s_] = 0; }
#pragma unroll 4
            for (int r = 0; r < R; r++) {
                longlong2 i2 = *(const longlong2*)(gImg + (size_t)r * D + 4 * d4);  // coalesced LDG.128
#pragma unroll
                for (int s_ = 0; s_ < 8; s_++) {
                    long long a = at[s_ * R + r];                                    // broadcast LDS.64
                    FMA2(accA[s_], i2.x, a);
                    FMA2(accB[s_], i2.y, a);
                }
            }
#pragma unroll
            for (int s_ = 0; s_ < 8; s_++) {
                float4 o;
                unpackf2(accA[s_], o.x, o.y);
                unpackf2(accB[s_], o.z, o.w);
                *(float4*)(gOut + (size_t)(tw * 8 + s_) * D + 4 * d4) = o;
            }
        }
    }
}

extern "C" void kernel_launch(void* const* d_in, const int* in_sizes, int n_in,
                              void* d_out, int out_size)
{
    const float* img = (const float*)d_in[0];   // (B, R, D) fp32
    const float* cap = (const float*)d_in[1];   // (B, T, D) fp32
    // d_in[2] = cap_mask, unused by the reference forward
    float* out = (float*)d_out;                 // (B, T, D) fp32

    cudaFuncSetAttribute(scan_hmma_kernel,
                         cudaFuncAttributeMaxDynamicSharedMemorySize, SMEM_BYTES);

    scan_hmma_kernel<<<B, 256, SMEM_BYTES>>>(img, cap, out);
}

// round 17
// speedup vs baseline: 2.6558x; 1.3862x over previous
#include <cuda_runtime.h>
#include <cuda_bf16.h>
#include <cstdint>

// Problem constants (fixed by the reference setup_inputs)
static constexpr int B = 256;
static constexpr int R = 36;
static constexpr int T = 64;
static constexpr int D = 1024;

static constexpr int KCH = 64;             // d-elements per staged chunk (128B bf16 rows)
static constexpr int NCH = D / KCH;        // 16 chunks

// Shared-memory byte offsets (within 128-aligned window)
static constexpr int OFF_CAP  = 0;                    // Phase A cap tile: 64 x 128B = 8192
static constexpr int OFF_IMG  = 8192;                 // Phase A img tile: 48 x 128B = 6144
static constexpr int OFF_SC   = 14336;                // scores fp32 [64][49] = 12544
static constexpr int OFF_NP   = 26880;                // norm partials 100x16 fp32 = 6400
static constexpr int OFF_NRM  = 33280;                // norms 100 fp32 (+pad) = 512
static constexpr int OFF_AH   = 33792;                // attn hi bf16 [64][48] = 6144
static constexpr int OFF_AL   = 39936;                // attn lo bf16 [64][48] = 6144
// Phase C img tiles reuse the dead Phase-A tile region:
static constexpr int OFF_IH   = 0;                    // img hi bf16 [48][128B] = 6144
static constexpr int OFF_IL   = 6144;                 // img lo bf16 [48][128B] = 6144
static constexpr int SMEM_BYTES = 46080 + 128;

#define SWZ(x) ((x) ^ (((x) >> 3) & 0x70))

// ---------------- helpers ----------------
__device__ __forceinline__ uint32_t smem_u32(const void* p) {
    uint32_t a;
    asm("{ .reg .u64 t; cvta.to.shared.u64 t, %1; cvt.u32.u64 %0, t; }" : "=r"(a) : "l"(p));
    return a;
}
__device__ __forceinline__ uint32_t cvt_bf2(float lo, float hi) {  // packs (lo,hi) in mem order
    uint32_t r;
    asm("cvt.rn.bf16x2.f32 %0, %1, %2;" : "=r"(r) : "f"(hi), "f"(lo));
    return r;
}
__device__ __forceinline__ void ldm_x4(uint32_t& r0, uint32_t& r1, uint32_t& r2, uint32_t& r3,
                                       uint32_t a) {
    asm volatile("ldmatrix.sync.aligned.m8n8.x4.shared.b16 {%0,%1,%2,%3}, [%4];"
                 : "=r"(r0), "=r"(r1), "=r"(r2), "=r"(r3) : "r"(a));
}
__device__ __forceinline__ void ldm_x4t(uint32_t& r0, uint32_t& r1, uint32_t& r2, uint32_t& r3,
                                        uint32_t a) {
    asm volatile("ldmatrix.sync.aligned.m8n8.x4.trans.shared.b16 {%0,%1,%2,%3}, [%4];"
                 : "=r"(r0), "=r"(r1), "=r"(r2), "=r"(r3) : "r"(a));
}
__device__ __forceinline__ void ldm_x2(uint32_t& r0, uint32_t& r1, uint32_t a) {
    asm volatile("ldmatrix.sync.aligned.m8n8.x2.shared.b16 {%0,%1}, [%2];"
                 : "=r"(r0), "=r"(r1) : "r"(a));
}
__device__ __forceinline__ void mma16816(float* d,
                                         const uint32_t* a,
                                         uint32_t b0, uint32_t b1) {
    asm volatile("mma.sync.aligned.m16n8k16.row.col.f32.bf16.bf16.f32 "
                 "{%0,%1,%2,%3}, {%4,%5,%6,%7}, {%8,%9}, {%0,%1,%2,%3};"
                 : "+f"(d[0]), "+f"(d[1]), "+f"(d[2]), "+f"(d[3])
                 : "r"(a[0]), "r"(a[1]), "r"(a[2]), "r"(a[3]), "r"(b0), "r"(b1));
}

extern "C" __global__ void __launch_bounds__(256, 2)
scan_hmma2_kernel(const float* __restrict__ img,
                  const float* __restrict__ cap,
                  float* __restrict__ out)
{
    extern __shared__ char smraw[];
    const uint32_t sbase = smem_u32(smraw);
    const uint32_t abase = (sbase + 127u) & ~127u;
    char* sm = smraw + (abase - sbase);

    float*          scS = (float*)(sm + OFF_SC);     // [64][49]
    float*          np  = (float*)(sm + OFF_NP);     // [100][16]
    float*          nrm = (float*)(sm + OFF_NRM);    // [0..35]=img, [36..99]=cap
    __nv_bfloat16*  aH  = (__nv_bfloat16*)(sm + OFF_AH);
    __nv_bfloat16*  aL  = (__nv_bfloat16*)(sm + OFF_AL);
    const uint32_t capBase = abase + OFF_CAP;
    const uint32_t imgBase = abase + OFF_IMG;

    const int b    = blockIdx.x;
    const int tid  = threadIdx.x;
    const int warp = tid >> 5;
    const int lane = tid & 31;
    const int tt   = warp >> 1;            // Phase A: t-tile of 16
    const int nh   = warp & 1;             // Phase A: n-half of 24 r

    const float* gImg = img + (size_t)b * R * D;
    const float* gCap = cap + (size_t)b * T * D;
    float*       gOut = out + (size_t)b * T * D;

    // ============ Phase A: scores = cap . img^T via HMMA (proven in R15) ============
    float C0[4] = {0, 0, 0, 0}, C1[4] = {0, 0, 0, 0}, C2[4] = {0, 0, 0, 0};
    float capN[4] = {0.f, 0.f, 0.f, 0.f};
    float imgN[3] = {0.f, 0.f, 0.f};

    const int aRow = tt * 16 + (lane & 15);
    const int aOff = (lane >> 4) << 4;
    const int bRow = nh * 24 + (lane & 7) + ((lane >> 4) << 3);
    const int bOff = ((lane >> 3) & 1) << 4;
    const int cRow = nh * 24 + 16 + (lane & 7);

#pragma unroll 1
    for (int c = 0; c < NCH; c++) {
        const int d0 = c * KCH;
#pragma unroll
        for (int m = 0; m < 4; m++) {
            const int i4  = tid + 256 * m;
            const int row = i4 >> 4, col4 = i4 & 15;
            float4 v = *(const float4*)(gCap + (size_t)row * D + d0 + 4 * col4);
            capN[m] += v.x * v.x + v.y * v.y + v.z * v.z + v.w * v.w;
            unsigned long long p = ((unsigned long long)cvt_bf2(v.z, v.w) << 32) | cvt_bf2(v.x, v.y);
            *(unsigned long long*)(sm + OFF_CAP + SWZ(row * 128 + col4 * 8)) = p;
        }
#pragma unroll
        for (int m = 0; m < 3; m++) {
            const int i4 = tid + 256 * m;
            if (i4 < R * 16) {
                const int row = i4 >> 4, col4 = i4 & 15;
                float4 v = *(const float4*)(gImg + (size_t)row * D + d0 + 4 * col4);
                imgN[m] += v.x * v.x + v.y * v.y + v.z * v.z + v.w * v.w;
                unsigned long long p = ((unsigned long long)cvt_bf2(v.z, v.w) << 32) | cvt_bf2(v.x, v.y);
                *(unsigned long long*)(sm + OFF_IMG + SWZ(row * 128 + col4 * 8)) = p;
            }
        }
        __syncthreads();

#pragma unroll
        for (int ks = 0; ks < 4; ks++) {
            const int kb = ks * 32;
            uint32_t a[4], b0, b1, b2, b3, b4, b5;
            ldm_x4(a[0], a[1], a[2], a[3], capBase + SWZ(aRow * 128 + kb + aOff));
            ldm_x4(b0, b1, b2, b3, imgBase + SWZ(bRow * 128 + kb + bOff));
            ldm_x2(b4, b5,         imgBase + SWZ(cRow * 128 + kb + bOff));
            mma16816(C0, a, b0, b1);
            mma16816(C1, a, b2, b3);
            mma16816(C2, a, b4, b5);
        }
        __syncthreads();
    }

    // write C frags -> scores[t][r] (stride 49)
    {
        const int row0 = tt * 16 + (lane >> 2);
        const int col0 = nh * 24 + (lane & 3) * 2;
        float* s0 = scS + row0 * 49 + col0;
        float* s8 = s0 + 8 * 49;
        s0[0] = C0[0];  s0[1] = C0[1];  s8[0] = C0[2];  s8[1] = C0[3];
        s0[8] = C1[0];  s0[9] = C1[1];  s8[8] = C1[2];  s8[9] = C1[3];
        s0[16] = C2[0]; s0[17] = C2[1]; s8[16] = C2[2]; s8[17] = C2[3];
    }
    {
        const int a = tid >> 4, l = tid & 15;
#pragma unroll
        for (int m = 0; m < 4; m++) np[(R + 16 * m + a) * 16 + l] = capN[m];
        np[(0 + a) * 16 + l]  = imgN[0];
        np[(16 + a) * 16 + l] = imgN[1];
        if (tid < 64) np[(32 + a) * 16 + l] = imgN[2];
    }
    __syncthreads();
    if (tid < R + T) {
        float s = 0.f;
#pragma unroll
        for (int j = 0; j < 16; j++) s += np[tid * 16 + j];
        nrm[tid] = sqrtf(s);
    }
    __syncthreads();

    // ============ Phase B: cosine scale + softmax, emit attn as bf16 hi/lo ============
    if (tid < T) {
        const float cn = nrm[R + tid];
        float s[R];
        float mx = -1e30f;
#pragma unroll
        for (int r = 0; r < R; r++) {
            float denom = fmaxf(nrm[r] * cn, 1e-8f);
            s[r] = scS[tid * 49 + r] / denom;
            mx = fmaxf(mx, s[r]);
        }
        float sum = 0.f;
#pragma unroll
        for (int r = 0; r < R; r++) { s[r] = expf(s[r] - mx); sum += s[r]; }
        const float inv = 1.f / sum;
        __nv_bfloat16* ah = aH + tid * 48;
        __nv_bfloat16* al = aL + tid * 48;
#pragma unroll
        for (int r = 0; r < R; r++) {
            float a = s[r] * inv;
            __nv_bfloat16 h = __float2bfloat16(a);
            ah[r] = h;
            al[r] = __float2bfloat16(a - __bfloat162float(h));
        }
#pragma unroll
        for (int r = R; r < 48; r++) { ah[r] = __float2bfloat16(0.f); al[r] = __float2bfloat16(0.f); }
    }
    __syncthreads();

    // ============ Phase C: out = attn(64x48) . img(48xD) via HMMA, 2-term bf16 split ============
    const int warpM = warp >> 1;           // m-tile of 16 t
    const int dhalf = warp & 1;            // 32-d half of each chunk

    // A fragments (attn hi/lo), loaded once; k-steps: r 0-15, 16-31, 32-47 (pads zeroed)
    uint32_t ah[3][4], al[3][4];
    {
        const uint32_t aBaseH = abase + OFF_AH + (warpM * 16 + (lane & 15)) * 96 + ((lane >> 4) << 4);
        const uint32_t aBaseL = abase + OFF_AL + (warpM * 16 + (lane & 15)) * 96 + ((lane >> 4) << 4);
#pragma unroll
        for (int ks = 0; ks < 3; ks++) {
            ldm_x4(ah[ks][0], ah[ks][1], ah[ks][2], ah[ks][3], aBaseH + ks * 32);
            ldm_x4(al[ks][0], al[ks][1], al[ks][2], al[ks][3], aBaseL + ks * 32);
        }
    }

    // zero img-tile pad rows 36-47 once (stale smem there could be NaN-pattern bits)
    for (int i = tid; i < 384; i += 256) {
        const int t_ = (i < 192) ? OFF_IH : OFF_IL;
        const int j  = (i < 192) ? i : i - 192;
        *(unsigned long long*)(sm + t_ + (36 + (j >> 4)) * 128 + (j & 15) * 8) = 0ull;
    }

    // B-frag ldmatrix addressing (trans): group g covers (k-half, n-half) quadrants
    const int bg   = lane >> 3;
    const int bRowC = (bg & 1) * 8 + (lane & 7);          // + ks*16
    const int bColC = dhalf * 64 + (bg >> 1) * 16;        // + nt16*32 (bytes)

#pragma unroll 1
    for (int c = 0; c < NCH; c++) {
        const int d0 = c * KCH;

        // stage img hi/lo tiles (rows 0-35)
#pragma unroll
        for (int m = 0; m < 3; m++) {
            const int i4 = tid + 256 * m;
            if (i4 < R * 16) {
                const int row = i4 >> 4, col4 = i4 & 15;
                float4 v = *(const float4*)(gImg + (size_t)row * D + d0 + 4 * col4);
                uint32_t h0 = cvt_bf2(v.x, v.y), h1 = cvt_bf2(v.z, v.w);
                float hx = __uint_as_float(h0 << 16), hy = __uint_as_float(h0 & 0xFFFF0000u);
                float hz = __uint_as_float(h1 << 16), hw = __uint_as_float(h1 & 0xFFFF0000u);
                uint32_t l0 = cvt_bf2(v.x - hx, v.y - hy), l1 = cvt_bf2(v.z - hz, v.w - hw);
                const int o = SWZ(row * 128 + col4 * 8);
                *(unsigned long long*)(sm + OFF_IH + o) = ((unsigned long long)h1 << 32) | h0;
                *(unsigned long long*)(sm + OFF_IL + o) = ((unsigned long long)l1 << 32) | l0;
            }
        }
        __syncthreads();

        float C[4][4];
#pragma unroll
        for (int j = 0; j < 4; j++)
#pragma unroll
            for (int q = 0; q < 4; q++) C[j][q] = 0.f;

#pragma unroll
        for (int ks = 0; ks < 3; ks++) {
#pragma unroll
            for (int nt = 0; nt < 2; nt++) {
                const int o = SWZ((ks * 16 + bRowC) * 128 + bColC + nt * 32);
                uint32_t bh0, bh1, bh2, bh3, bl0, bl1, bl2, bl3;
                ldm_x4t(bh0, bh1, bh2, bh3, abase + OFF_IH + o);
                ldm_x4t(bl0, bl1, bl2, bl3, abase + OFF_IL + o);
                // C += Ah.Bh + Ah.Bl + Al.Bh   (lo.lo dropped, ~2^-16)
                mma16816(C[2 * nt],     ah[ks], bh0, bh1);
                mma16816(C[2 * nt],     ah[ks], bl0, bl1);
                mma16816(C[2 * nt],     al[ks], bh0, bh1);
                mma16816(C[2 * nt + 1], ah[ks], bh2, bh3);
                mma16816(C[2 * nt + 1], ah[ks], bl2, bl3);
                mma16816(C[2 * nt + 1], al[ks], bh2, bh3);
            }
        }
        __syncthreads();   // all ldmatrix done -> tiles reusable next chunk

        // store C frags -> out
        {
            const int row0 = warpM * 16 + (lane >> 2);
            const int col0 = d0 + dhalf * 32 + (lane & 3) * 2;
#pragma unroll
            for (int j = 0; j < 4; j++) {
                float* p0 = gOut + (size_t)row0 * D + col0 + j * 8;
                float* p8 = p0 + 8 * D;
                *(float2*)p0 = make_float2(C[j][0], C[j][1]);
                *(float2*)p8 = make_float2(C[j][2], C[j][3]);
            }
        }
    }
}

extern "C" void kernel_launch(void* const* d_in, const int* in_sizes, int n_in,
                              void* d_out, int out_size)
{
    const float* img = (const float*)d_in[0];   // (B, R, D) fp32
    const float* cap = (const float*)d_in[1];   // (B, T, D) fp32
    // d_in[2] = cap_mask, unused by the reference forward
    float* out = (float*)d_out;                 // (B, T, D) fp32

    cudaFuncSetAttribute(scan_hmma2_kernel,
                         cudaFuncAttributeMaxDynamicSharedMemorySize, SMEM_BYTES);

    scan_hmma2_kernel<<<B, 256, SMEM_BYTES>>>(img, cap, out);
}